// round 5
// baseline (speedup 1.0000x reference)
#include <cuda_runtime.h>

typedef unsigned long long u64;

#define HH    56
#define WW    56
#define CIN   64
#define COUT  64
#define TILE  8

// ---- packed f32x2 helpers (sm_103a) ----
__device__ __forceinline__ u64 addx2(u64 a, u64 b) {
    u64 r; asm("add.rn.f32x2 %0, %1, %2;" : "=l"(r) : "l"(a), "l"(b)); return r;
}
__device__ __forceinline__ u64 pack2(float lo, float hi) {
    u64 r; asm("mov.b64 %0, {%1, %2};" : "=l"(r) : "f"(lo), "f"(hi)); return r;
}
__device__ __forceinline__ void unpack2(u64 v, float& lo, float& hi) {
    asm("mov.b64 {%0, %1}, %2;" : "=f"(lo), "=f"(hi) : "l"(v));
}
__device__ __forceinline__ u64 abs2(u64 v) {  // 2x LOP3 on alu pipe
    return v & 0x7FFFFFFF7FFFFFFFull;
}

// x chunks stored PRE-PAIRED stride-4: sxp[ci][row][t] = (x[col=t], x[col=t+4]),
// t=0..5, halo cols 0..9. Every kw shift reads consecutive aligned u64 -> no MOVs.
__shared__ __align__(16) u64 sxp_buf[2][8][10][6];    // 2 x 3.84 KB
__shared__ __align__(16) u64 swd_buf[2][8][9][32];    // dup (-w,-w), 2 x 18.4 KB

__device__ __forceinline__ void stage_chunk(
    int buf, int c8, int tid, int tx0, int ty0, int cobase,
    const float* __restrict__ xn, const float* __restrict__ w)
{
    // ---- x chunk: 8 ci x 10 rows x 6 stride-4 pairs ----
    #pragma unroll
    for (int it = 0; it < 4; ++it) {                  // 480 / 128 = 3.75
        int idx = it * 128 + tid;
        if (idx < 480) {
            int ci_l = idx / 60;
            int r    = idx - ci_l * 60;
            int row  = r / 6;
            int t    = r - row * 6;
            int gy   = ty0 + row - 1;
            int gx0  = tx0 + t - 1;
            float lo = 0.0f, hi = 0.0f;
            if ((unsigned)gy < (unsigned)HH) {
                const float* base = &xn[((c8 * 8 + ci_l) * HH + gy) * WW];
                if ((unsigned)gx0 < (unsigned)WW)       lo = base[gx0];
                if ((unsigned)(gx0 + 4) < (unsigned)WW) hi = base[gx0 + 4];
            }
            sxp_buf[buf][ci_l][row][t] = pack2(lo, hi);
        }
    }
    // ---- weights: 8 ci x 9 k x 32 co, negated + duplicated ----
    #pragma unroll
    for (int it = 0; it < 18; ++it) {                 // 2304 / 128
        int idx  = it * 128 + tid;
        int co   = idx & 31;
        int rest = idx >> 5;                          // 0..71
        int k    = rest % 9;
        int ci_l = rest / 9;
        float wv = -w[((cobase + co) * CIN + c8 * 8 + ci_l) * 9 + k];
        swd_buf[buf][ci_l][k][co] = pack2(wv, wv);
    }
}

// CTA: one n, one 8x8 tile, 32 output channels.
// 128 threads: py = tid&7 (row), cg = tid>>3 (2 channels each).
// Thread: 8 pixels as 4 stride-4 f32x2 pairs x 2 channels -> 8 u64 acc.
__global__ void __launch_bounds__(128, 5)
adder2d_kernel(const float* __restrict__ x,
               const float* __restrict__ w,
               float* __restrict__ out)
{
    const int tid  = threadIdx.x;
    const int py   = tid & 7;
    const int cg   = tid >> 3;
    const int co2  = cg * 2;

    const int tx0    = blockIdx.x * TILE;
    const int ty0    = blockIdx.y * TILE;
    const int n      = blockIdx.z >> 1;
    const int cobase = (blockIdx.z & 1) * 32;

    const float* xn = x + (size_t)n * CIN * HH * WW;

    u64 acc[2][4];
    #pragma unroll
    for (int c = 0; c < 2; ++c)
        #pragma unroll
        for (int p = 0; p < 4; ++p) acc[c][p] = 0ull;

    stage_chunk(0, 0, tid, tx0, ty0, cobase, xn, w);

    for (int c8 = 0; c8 < 8; ++c8) {
        const int cb = c8 & 1;
        __syncthreads();   // buf[cb] staged; buf[cb^1] readers done

        if (c8 < 7)
            stage_chunk(cb ^ 1, c8 + 1, tid, tx0, ty0, cobase, xn, w);

        #pragma unroll 2
        for (int ci_l = 0; ci_l < 8; ++ci_l) {
            #pragma unroll
            for (int kh = 0; kh < 3; ++kh) {
                // prefetch: 6 x-pairs + 3 weight vectors (MLP 9), then pure math
                const u64* xp = &sxp_buf[cb][ci_l][py + kh][0];
                u64 x0 = xp[0], x1 = xp[1], x2 = xp[2],
                    x3 = xp[3], x4 = xp[4], x5 = xp[5];
                ulonglong2 w0 = *(const ulonglong2*)&swd_buf[cb][ci_l][kh * 3 + 0][co2];
                ulonglong2 w1 = *(const ulonglong2*)&swd_buf[cb][ci_l][kh * 3 + 1][co2];
                ulonglong2 w2 = *(const ulonglong2*)&swd_buf[cb][ci_l][kh * 3 + 2][co2];

                #pragma unroll
                for (int kw = 0; kw < 3; ++kw) {
                    u64 p0 = (kw == 0) ? x0 : (kw == 1) ? x1 : x2;
                    u64 p1 = (kw == 0) ? x1 : (kw == 1) ? x2 : x3;
                    u64 p2 = (kw == 0) ? x2 : (kw == 1) ? x3 : x4;
                    u64 p3 = (kw == 0) ? x3 : (kw == 1) ? x4 : x5;
                    ulonglong2 wp = (kw == 0) ? w0 : (kw == 1) ? w1 : w2;
                    acc[0][0] = addx2(acc[0][0], abs2(addx2(p0, wp.x)));
                    acc[0][1] = addx2(acc[0][1], abs2(addx2(p1, wp.x)));
                    acc[0][2] = addx2(acc[0][2], abs2(addx2(p2, wp.x)));
                    acc[0][3] = addx2(acc[0][3], abs2(addx2(p3, wp.x)));
                    acc[1][0] = addx2(acc[1][0], abs2(addx2(p0, wp.y)));
                    acc[1][1] = addx2(acc[1][1], abs2(addx2(p1, wp.y)));
                    acc[1][2] = addx2(acc[1][2], abs2(addx2(p2, wp.y)));
                    acc[1][3] = addx2(acc[1][3], abs2(addx2(p3, wp.y)));
                }
            }
        }
    }

    // ---- epilogue: acc[c][j] holds output pixels (j, j+4) ----
    #pragma unroll
    for (int c = 0; c < 2; ++c) {
        float f[8];
        #pragma unroll
        for (int j = 0; j < 4; ++j) {
            float lo, hi;
            unpack2(acc[c][j], lo, hi);
            f[j]     = -lo;
            f[j + 4] = -hi;
        }
        float* o = out + (((size_t)n * COUT + cobase + co2 + c) * HH + (ty0 + py)) * WW + tx0;
        ((float4*)o)[0] = make_float4(f[0], f[1], f[2], f[3]);
        ((float4*)o)[1] = make_float4(f[4], f[5], f[6], f[7]);
    }
}

extern "C" void kernel_launch(void* const* d_in, const int* in_sizes, int n_in,
                              void* d_out, int out_size)
{
    const float* x = (const float*)d_in[0];
    const float* w = (const float*)d_in[1];
    float* out     = (float*)d_out;

    dim3 grid(WW / TILE, HH / TILE, 32);   // 7 x 7 x (16 n * 2 co-halves) = 1568 CTAs
    adder2d_kernel<<<grid, 128>>>(x, w, out);
}

// round 6
// speedup vs baseline: 1.0216x; 1.0216x over previous
#include <cuda_runtime.h>

typedef unsigned long long u64;

#define HH    56
#define WW    56
#define CIN   64
#define COUT  64
#define TILE  8

// ---- packed f32x2 helpers (sm_103a) ----
__device__ __forceinline__ u64 addx2(u64 a, u64 b) {
    u64 r; asm("add.rn.f32x2 %0, %1, %2;" : "=l"(r) : "l"(a), "l"(b)); return r;
}
__device__ __forceinline__ u64 pack2(float lo, float hi) {
    u64 r; asm("mov.b64 %0, {%1, %2};" : "=l"(r) : "f"(lo), "f"(hi)); return r;
}
__device__ __forceinline__ void unpack2(u64 v, float& lo, float& hi) {
    asm("mov.b64 {%0, %1}, %2;" : "=f"(lo), "=f"(hi) : "l"(v));
}
__device__ __forceinline__ u64 abs2(u64 v) {  // 2x LOP3 on alu pipe
    return v & 0x7FFFFFFF7FFFFFFFull;
}

// x stored PRE-PAIRED stride-4: sxp[ci][row][t] = (x[col=t], x[col=t+4]), t=0..5.
// Single buffer: 3.84 KB + 18.4 KB = 22.3 KB -> 8 CTAs/SM.
__shared__ __align__(16) u64 sxp[8][10][6];
__shared__ __align__(16) u64 swd[8][9][32];   // dup (-w,-w) pairs

// CTA: one n, one 8x8 tile, 32 output channels.
// 128 threads: py = tid&7 (row), cg = tid>>3 (2 channels each).
// Thread: 8 pixels as 4 stride-4 f32x2 pairs x 2 channels -> 8 u64 acc.
__global__ void __launch_bounds__(128, 8)
adder2d_kernel(const float* __restrict__ x,
               const float* __restrict__ w,
               float* __restrict__ out)
{
    const int tid  = threadIdx.x;
    const int py   = tid & 7;
    const int co2  = (tid >> 3) * 2;

    const int tx0    = blockIdx.x * TILE;
    const int ty0    = blockIdx.y * TILE;
    const int n      = blockIdx.z >> 1;
    const int cobase = (blockIdx.z & 1) * 32;

    const float* xn = x + (size_t)n * CIN * HH * WW;

    u64 acc[2][4];
    #pragma unroll
    for (int c = 0; c < 2; ++c)
        #pragma unroll
        for (int p = 0; p < 4; ++p) acc[c][p] = 0ull;

    for (int c8 = 0; c8 < 8; ++c8) {
        __syncthreads();   // previous chunk's readers done

        // ---- stage x chunk: 8 ci x 10 rows x 6 stride-4 pairs ----
        #pragma unroll
        for (int it = 0; it < 4; ++it) {              // 480 / 128
            int idx = it * 128 + tid;
            if (idx < 480) {
                int ci_l = idx / 60;
                int r    = idx - ci_l * 60;
                int row  = r / 6;
                int t    = r - row * 6;
                int gy   = ty0 + row - 1;
                int gx0  = tx0 + t - 1;
                float lo = 0.0f, hi = 0.0f;
                if ((unsigned)gy < (unsigned)HH) {
                    const float* base = &xn[((c8 * 8 + ci_l) * HH + gy) * WW];
                    if ((unsigned)gx0 < (unsigned)WW)       lo = base[gx0];
                    if ((unsigned)(gx0 + 4) < (unsigned)WW) hi = base[gx0 + 4];
                }
                sxp[ci_l][row][t] = pack2(lo, hi);
            }
        }
        // ---- stage weights: 8 ci x 9 k x 32 co, negated + duplicated ----
        #pragma unroll
        for (int it = 0; it < 18; ++it) {             // 2304 / 128
            int idx  = it * 128 + tid;
            int co   = idx & 31;
            int rest = idx >> 5;                      // 0..71
            int k    = rest % 9;
            int ci_l = rest / 9;
            float wv = -w[((cobase + co) * CIN + c8 * 8 + ci_l) * 9 + k];
            swd[ci_l][k][co] = pack2(wv, wv);
        }
        __syncthreads();

        // ---- compute (unroll 1 over ci keeps live ranges short) ----
        for (int ci_l = 0; ci_l < 8; ++ci_l) {
            #pragma unroll
            for (int kh = 0; kh < 3; ++kh) {
                const u64* xp = &sxp[ci_l][py + kh][0];
                u64 x0 = xp[0], x1 = xp[1], x2 = xp[2],
                    x3 = xp[3], x4 = xp[4], x5 = xp[5];

                #pragma unroll
                for (int kw = 0; kw < 3; ++kw) {
                    u64 p0 = (kw == 0) ? x0 : (kw == 1) ? x1 : x2;
                    u64 p1 = (kw == 0) ? x1 : (kw == 1) ? x2 : x3;
                    u64 p2 = (kw == 0) ? x2 : (kw == 1) ? x3 : x4;
                    u64 p3 = (kw == 0) ? x3 : (kw == 1) ? x4 : x5;
                    // point-of-use LDS.128: both channels' (-w,-w) pairs
                    ulonglong2 wp = *(const ulonglong2*)&swd[ci_l][kh * 3 + kw][co2];
                    acc[0][0] = addx2(acc[0][0], abs2(addx2(p0, wp.x)));
                    acc[0][1] = addx2(acc[0][1], abs2(addx2(p1, wp.x)));
                    acc[0][2] = addx2(acc[0][2], abs2(addx2(p2, wp.x)));
                    acc[0][3] = addx2(acc[0][3], abs2(addx2(p3, wp.x)));
                    acc[1][0] = addx2(acc[1][0], abs2(addx2(p0, wp.y)));
                    acc[1][1] = addx2(acc[1][1], abs2(addx2(p1, wp.y)));
                    acc[1][2] = addx2(acc[1][2], abs2(addx2(p2, wp.y)));
                    acc[1][3] = addx2(acc[1][3], abs2(addx2(p3, wp.y)));
                }
            }
        }
    }

    // ---- epilogue: acc[c][j] holds output pixels (j, j+4) ----
    #pragma unroll
    for (int c = 0; c < 2; ++c) {
        float f[8];
        #pragma unroll
        for (int j = 0; j < 4; ++j) {
            float lo, hi;
            unpack2(acc[c][j], lo, hi);
            f[j]     = -lo;
            f[j + 4] = -hi;
        }
        float* o = out + (((size_t)n * COUT + cobase + co2 + c) * HH + (ty0 + py)) * WW + tx0;
        ((float4*)o)[0] = make_float4(f[0], f[1], f[2], f[3]);
        ((float4*)o)[1] = make_float4(f[4], f[5], f[6], f[7]);
    }
}

extern "C" void kernel_launch(void* const* d_in, const int* in_sizes, int n_in,
                              void* d_out, int out_size)
{
    const float* x = (const float*)d_in[0];
    const float* w = (const float*)d_in[1];
    float* out     = (float*)d_out;

    dim3 grid(WW / TILE, HH / TILE, 32);   // 7 x 7 x (16 n * 2 co-halves) = 1568 CTAs
    adder2d_kernel<<<grid, 128>>>(x, w, out);
}